// round 17
// baseline (speedup 1.0000x reference)
#include <cuda_runtime.h>
#include <cuda_fp16.h>
#include <cstdint>

// Problem constants
#define N_ATOMS 100000
#define N_EDGES 1000000
#define HID 64
#define OUTD 128
#define NTILES 1563          // ceil(N_ATOMS / 64)
#define PROJ_GRID 296        // 2 blocks/SM x 148

#define SCAN_T 512
#define SCAN_ITEMS (N_ATOMS + 1)
#define SCAN_NB ((SCAN_ITEMS + SCAN_T - 1) / SCAN_T)

// Scratch (device globals: allocation-free rule)
__device__ __half g_xh[N_ATOMS * HID];     // node features, fp16 (MMA A operand)
__device__ __half g_gtop[N_ATOMS * HID];   // 0.5*(x @ Wg_top + b_gate)
__device__ uint2  g_gl[N_ATOMS * 32];      // per (node,lane): {0.5*gbot half2, linh half2}
__device__ __half g_wf[3 * 64 * 192];      // fused fp16 weights per layer
__device__ float  g_pooled[HID];

// Edge CSR (built per launch by counting sort)
__device__ int g_cnt[SCAN_ITEMS];
__device__ int g_off[SCAN_ITEMS];
__device__ int g_cur[N_ATOMS];
__device__ int g_part[SCAN_NB];
__device__ int g_scol[N_EDGES];

static __device__ __forceinline__ uint32_t cvta_s(const void* p) {
    uint32_t r;
    asm("{ .reg .u64 t; cvta.to.shared.u64 t, %1; cvt.u32.u64 %0, t; }" : "=r"(r) : "l"(p));
    return r;
}

// ---------------------------------------------------------------------------
// 0. Weight preconvert + zero g_cnt/g_pooled (runs FIRST)
// ---------------------------------------------------------------------------
__global__ void __launch_bounds__(256) wconv_kernel(const float* __restrict__ Wg,
                                                    const float* __restrict__ Wl) {
    int i = blockIdx.x * 256 + threadIdx.x;
    if (i < 3 * 64 * 192) {
        int lay = i / (64 * 192);
        int rem = i - lay * (64 * 192);
        int k = rem / 192, c = rem - k * 192;
        float w;
        if (c < 64)       w = Wg[lay * 128 * 64 + k * 64 + c];
        else if (c < 128) w = Wg[lay * 128 * 64 + (64 + k) * 64 + (c - 64)];
        else              w = Wl[lay * 64 * 64 + k * 64 + (c - 128)];
        g_wf[i] = __float2half(w);
    }
    if (i < SCAN_ITEMS) g_cnt[i] = 0;
    if (i < HID) g_pooled[i] = 0.0f;
}

// ---------------------------------------------------------------------------
// 1. Embedding lookup (vectorized: 8 ch/thread, STG.128) + edge histogram
// ---------------------------------------------------------------------------
__global__ void __launch_bounds__(256) embed_kernel(const int* __restrict__ an,
                                                    const float* __restrict__ emb,
                                                    const int* __restrict__ ei) {
    int i = blockIdx.x * 256 + threadIdx.x;
    if (i < N_ATOMS * 8) {
        int v = i >> 3, ch = i & 7;
        const float4* e4 = reinterpret_cast<const float4*>(
            emb + (size_t)__ldg(&an[v]) * HID + ch * 8);
        float4 f0 = __ldg(&e4[0]), f1 = __ldg(&e4[1]);
        __half2 h[4];
        h[0] = __floats2half2_rn(f0.x, f0.y);
        h[1] = __floats2half2_rn(f0.z, f0.w);
        h[2] = __floats2half2_rn(f1.x, f1.y);
        h[3] = __floats2half2_rn(f1.z, f1.w);
        *reinterpret_cast<uint4*>(g_xh + (size_t)v * HID + ch * 8) =
            *reinterpret_cast<uint4*>(h);
    }
    if (i < N_EDGES) atomicAdd(&g_cnt[ei[i]], 1);
}

// ---------------------------------------------------------------------------
// 2. Scan (a: block sums; c: fused partial-scan + local scan) + scatter
// ---------------------------------------------------------------------------
__global__ void __launch_bounds__(SCAN_T) scan_a_kernel() {
    __shared__ int s[SCAN_T];
    int t = threadIdx.x;
    int i = blockIdx.x * SCAN_T + t;
    s[t] = (i < SCAN_ITEMS) ? g_cnt[i] : 0;
    __syncthreads();
    for (int d = SCAN_T / 2; d > 0; d >>= 1) {
        if (t < d) s[t] += s[t + d];
        __syncthreads();
    }
    if (t == 0) g_part[blockIdx.x] = s[0];
}

__global__ void __launch_bounds__(SCAN_T) scan_c_kernel() {
    __shared__ int s[SCAN_T];
    __shared__ int p[256];
    int t = threadIdx.x;
    int i = blockIdx.x * SCAN_T + t;

    if (t < 256) p[t] = (t < SCAN_NB) ? g_part[t] : 0;
    __syncthreads();
    for (int d = 1; d < 256; d <<= 1) {
        int a = 0;
        if (t < 256 && t >= d) a = p[t - d];
        __syncthreads();
        if (t < 256) p[t] += a;
        __syncthreads();
    }
    int prefix = (blockIdx.x == 0) ? 0 : p[blockIdx.x - 1];

    int v = (i < SCAN_ITEMS) ? g_cnt[i] : 0;
    s[t] = v;
    __syncthreads();
    for (int d = 1; d < SCAN_T; d <<= 1) {
        int a = (t >= d) ? s[t - d] : 0;
        __syncthreads();
        s[t] += a;
        __syncthreads();
    }
    int off = prefix + s[t] - v;  // exclusive
    if (i < SCAN_ITEMS) g_off[i] = off;
    if (i < N_ATOMS)    g_cur[i] = off;
}

__global__ void __launch_bounds__(256) scatter_kernel(const int* __restrict__ ei) {
    int e = blockIdx.x * 256 + threadIdx.x;
    if (e < N_EDGES) {
        int r = ei[e];
        int c = ei[N_EDGES + e];
        int p = atomicAdd(&g_cur[r], 1);
        g_scol[p] = c;
    }
}

// ---------------------------------------------------------------------------
// 3. Persistent tensor-core projection, v3 (r16-proven): 64-node tiles,
//    256 thr, 2 blocks/SM. 8 warps = 2(m) x 4(n).
// ---------------------------------------------------------------------------
#define WS_STRIDE 200
#define XS_STRIDE 72
#define STG_STRIDE 72
#define WS_BYTES   (64 * WS_STRIDE * 2)          // 25600
#define XS_OFF     WS_BYTES
#define XS_BUF_BYTES (64 * XS_STRIDE * 2)        // 9216
#define STG_OFF    (XS_OFF + 2 * XS_BUF_BYTES)   // 44032
#define SG_GT_OFF  STG_OFF
#define SG_GB_OFF  (STG_OFF + 64 * STG_STRIDE * 2)
#define SG_LN_OFF  (STG_OFF + 2 * 64 * STG_STRIDE * 2)
#define BIAS_OFF   (STG_OFF + 3 * 64 * STG_STRIDE * 2)   // 71680
#define PROJ_SMEM  (BIAS_OFF + 512)                       // 72192

static __device__ __forceinline__ void prefetch_tile(int tile, int buf, int tid,
                                                     uint32_t xs_base_u) {
    int n0 = tile * 64;
    #pragma unroll
    for (int p = 0; p < 2; p++) {
        int idx = tid + p * 256;
        int r = idx >> 3, grp = idx & 7;
        int node = n0 + r;
        int node_c = node < N_ATOMS ? node : N_ATOMS - 1;
        uint32_t dst = xs_base_u + buf * XS_BUF_BYTES + (r * XS_STRIDE + grp * 8) * 2;
        const void* src = g_xh + (size_t)node_c * HID + grp * 8;
        int sz = (node < N_ATOMS) ? 16 : 0;
        asm volatile("cp.async.cg.shared.global [%0], [%1], 16, %2;"
                     :: "r"(dst), "l"(src), "r"(sz));
    }
    asm volatile("cp.async.commit_group;");
}

__global__ void __launch_bounds__(256, 2) proj_kernel(int layer,
                                                      const float* __restrict__ bg,
                                                      const float* __restrict__ bl) {
    extern __shared__ __align__(16) char smraw[];
    __half* ws    = (__half*)smraw;                   // [64][200]
    __half* sg_gt = (__half*)(smraw + SG_GT_OFF);     // [64][72]
    __half* sg_gb = (__half*)(smraw + SG_GB_OFF);     // [64][72]
    __half* sg_ln = (__half*)(smraw + SG_LN_OFF);     // [64][72]
    float*  bgs   = (float*)(smraw + BIAS_OFF);
    float*  bls   = bgs + 64;

    const int tid = threadIdx.x;
    const __half* wf = g_wf + layer * 64 * 192;

    for (int i = tid; i < 1536; i += 256) {
        int k = i / 24, grp = i - k * 24;
        *reinterpret_cast<uint4*>(ws + k * WS_STRIDE + grp * 8) =
            *reinterpret_cast<const uint4*>(wf + k * 192 + grp * 8);
    }
    if (tid < 64) { bgs[tid] = bg[tid]; bls[tid] = bl[tid]; }

    const uint32_t xs_base_u = cvta_s(smraw + XS_OFF);
    const uint32_t ws_u = cvta_s(ws);

    const int wid = tid >> 5, l = tid & 31;
    const int wm = wid & 1;    // rows wm*32 .. +31
    const int wn = wid >> 1;   // cols wn*48 .. +47
    const uint32_t b_base = ws_u + ((l & 15) * WS_STRIDE + wn * 48) * 2;
    const int qid = l >> 2, tig = l & 3;

    int t = blockIdx.x;
    int buf = 0;
    if (t < NTILES) prefetch_tile(t, 0, tid, xs_base_u);

    while (t < NTILES) {
        int tn = t + PROJ_GRID;
        asm volatile("cp.async.wait_group 0;");
        __syncthreads();

        float acc[2][6][4];
        #pragma unroll
        for (int mi = 0; mi < 2; mi++)
            #pragma unroll
            for (int ni = 0; ni < 6; ni++)
                #pragma unroll
                for (int q = 0; q < 4; q++) acc[mi][ni][q] = 0.0f;

        const uint32_t a_base = xs_base_u + buf * XS_BUF_BYTES +
                                ((wm * 32 + (l & 15)) * XS_STRIDE + (l >> 4) * 8) * 2;
        #pragma unroll
        for (int kk = 0; kk < 4; kk++) {
            uint32_t b[6][2];
            uint32_t bstep = b_base + kk * 16 * WS_STRIDE * 2;
            #pragma unroll
            for (int ni = 0; ni < 6; ni++) {
                asm volatile("ldmatrix.sync.aligned.m8n8.x2.trans.shared.b16 {%0,%1}, [%2];"
                             : "=r"(b[ni][0]), "=r"(b[ni][1]) : "r"(bstep + ni * 8 * 2));
            }
            uint32_t astep = a_base + kk * 16 * 2;
            #pragma unroll
            for (int mi = 0; mi < 2; mi++) {
                uint32_t a0, a1, a2, a3;
                asm volatile("ldmatrix.sync.aligned.m8n8.x4.shared.b16 {%0,%1,%2,%3}, [%4];"
                             : "=r"(a0), "=r"(a1), "=r"(a2), "=r"(a3)
                             : "r"(astep + mi * 16 * XS_STRIDE * 2));
                #pragma unroll
                for (int ni = 0; ni < 6; ni++) {
                    asm volatile(
                        "mma.sync.aligned.m16n8k16.row.col.f32.f16.f16.f32 "
                        "{%0,%1,%2,%3},{%4,%5,%6,%7},{%8,%9},{%0,%1,%2,%3};"
                        : "+f"(acc[mi][ni][0]), "+f"(acc[mi][ni][1]),
                          "+f"(acc[mi][ni][2]), "+f"(acc[mi][ni][3])
                        : "r"(a0), "r"(a1), "r"(a2), "r"(a3), "r"(b[ni][0]), "r"(b[ni][1]));
                }
            }
        }

        if (tn < NTILES) prefetch_tile(tn, buf ^ 1, tid, xs_base_u);

        // Stage fragments (fp16; gtop/gbot pre-scaled by 0.5 for f16x2 tanh)
        #pragma unroll
        for (int mi = 0; mi < 2; mi++) {
            int r0 = wm * 32 + mi * 16 + qid;
            int r1 = r0 + 8;
            #pragma unroll
            for (int ni = 0; ni < 6; ni++) {
                int c = wn * 48 + ni * 8 + tig * 2;
                float d0 = acc[mi][ni][0], d1 = acc[mi][ni][1];
                float d2 = acc[mi][ni][2], d3 = acc[mi][ni][3];
                if (c < 64) {
                    float b0v = bgs[c], b1v = bgs[c + 1];
                    *reinterpret_cast<__half2*>(sg_gt + r0 * STG_STRIDE + c) =
                        __floats2half2_rn(0.5f * (d0 + b0v), 0.5f * (d1 + b1v));
                    *reinterpret_cast<__half2*>(sg_gt + r1 * STG_STRIDE + c) =
                        __floats2half2_rn(0.5f * (d2 + b0v), 0.5f * (d3 + b1v));
                } else if (c < 128) {
                    int cc = c - 64;
                    *reinterpret_cast<__half2*>(sg_gb + r0 * STG_STRIDE + cc) =
                        __floats2half2_rn(0.5f * d0, 0.5f * d1);
                    *reinterpret_cast<__half2*>(sg_gb + r1 * STG_STRIDE + cc) =
                        __floats2half2_rn(0.5f * d2, 0.5f * d3);
                } else {
                    int cc = c - 128;
                    float b0v = bls[cc], b1v = bls[cc + 1];
                    *reinterpret_cast<__half2*>(sg_ln + r0 * STG_STRIDE + cc) =
                        __floats2half2_rn(d0 + b0v, d1 + b1v);
                    *reinterpret_cast<__half2*>(sg_ln + r1 * STG_STRIDE + cc) =
                        __floats2half2_rn(d2 + b0v, d3 + b1v);
                }
            }
        }
        __syncthreads();

        const int node0 = t * 64;
        // gtop write-out: 512 uint4 chunks
        #pragma unroll
        for (int p = 0; p < 2; p++) {
            int cidx = tid + p * 256;
            int r = cidx >> 3, grp = cidx & 7;
            int node = node0 + r;
            if (node < N_ATOMS) {
                uint4 vt = *reinterpret_cast<uint4*>(sg_gt + r * STG_STRIDE + grp * 8);
                *reinterpret_cast<uint4*>(g_gtop + (size_t)node * HID + grp * 8) = vt;
            }
        }
        // interleaved {gbot, linh} write-out: 2048 uint2
        #pragma unroll
        for (int p = 0; p < 8; p++) {
            int cidx = tid + p * 256;
            int r = cidx >> 5, ln = cidx & 31;
            int node = node0 + r;
            if (node < N_ATOMS) {
                uint2 v;
                v.x = *reinterpret_cast<uint32_t*>(sg_gb + r * STG_STRIDE + 2 * ln);
                v.y = *reinterpret_cast<uint32_t*>(sg_ln + r * STG_STRIDE + 2 * ln);
                g_gl[(size_t)node * 32 + ln] = v;
            }
        }

        t = tn;
        buf ^= 1;
    }
}

// ---------------------------------------------------------------------------
// 4. Gather-aggregate + fused node update, half-warp edition.
//    Warp = 1 node. Lanes 0-15 process edge A, lanes 16-31 edge B (2 edges
//    per iteration); each lane covers 4 channels via one LDG.128 from g_gl.
//    Cross-half shfl reduction at the end; half 0 writes x.
// ---------------------------------------------------------------------------
__global__ void __launch_bounds__(256) gather_kernel() {
    int w = (blockIdx.x * 256 + threadIdx.x) >> 5;
    int l = threadIdx.x & 31;
    if (w >= N_ATOMS) return;
    const int half = l >> 4;
    const int hl = l & 15;

    int beg = __ldg(&g_off[w]);
    int end = __ldg(&g_off[w + 1]);

    // gt for channels 4hl..4hl+3
    uint2 gtu = *reinterpret_cast<const uint2*>(g_gtop + (size_t)w * HID + 4 * hl);
    __half2 gt0 = *reinterpret_cast<__half2*>(&gtu.x);
    __half2 gt1 = *reinterpret_cast<__half2*>(&gtu.y);

    const uint4* gl4 = reinterpret_cast<const uint4*>(g_gl);

    float4 acc = make_float4(0.0f, 0.0f, 0.0f, 0.0f);
    if (half == 0) {   // self linh term added once
        uint4 sv = __ldg(&gl4[(size_t)w * 16 + hl]);
        float2 s0 = __half22float2(*reinterpret_cast<__half2*>(&sv.y));
        float2 s1 = __half22float2(*reinterpret_cast<__half2*>(&sv.w));
        acc.x = s0.x; acc.y = s0.y; acc.z = s1.x; acc.w = s1.y;
    }

    for (int base = beg; base < end; base += 32) {
        int myc = (base + l < end) ? g_scol[base + l] : 0;
        int m = min(32, end - base);
        #pragma unroll 4
        for (int j0 = 0; j0 < m; j0 += 2) {
            int cc = __shfl_sync(0xffffffffu, myc, j0 + half);
            bool valid = (j0 + half) < m;
            uint4 v = make_uint4(0u, 0u, 0u, 0u);
            if (valid) v = __ldg(&gl4[(size_t)cc * 16 + hl]);
            __half2 gb0 = *reinterpret_cast<__half2*>(&v.x);
            __half2 lh0 = *reinterpret_cast<__half2*>(&v.y);
            __half2 gb1 = *reinterpret_cast<__half2*>(&v.z);
            __half2 lh1 = *reinterpret_cast<__half2*>(&v.w);
            __half2 pre0 = __hadd2(gt0, gb0);
            __half2 pre1 = __hadd2(gt1, gb1);
            uint32_t th0u, th1u;
            asm("tanh.approx.f16x2 %0, %1;"
                : "=r"(th0u) : "r"(*reinterpret_cast<uint32_t*>(&pre0)));
            asm("tanh.approx.f16x2 %0, %1;"
                : "=r"(th1u) : "r"(*reinterpret_cast<uint32_t*>(&pre1)));
            __half2 msg0 = __hfma2(*reinterpret_cast<__half2*>(&th0u), lh0, lh0);
            __half2 msg1 = __hfma2(*reinterpret_cast<__half2*>(&th1u), lh1, lh1);
            float2 m0 = __half22float2(msg0);
            float2 m1 = __half22float2(msg1);
            acc.x += 0.5f * m0.x;
            acc.y += 0.5f * m0.y;
            acc.z += 0.5f * m1.x;
            acc.w += 0.5f * m1.y;
        }
    }

    // reduce edge-B half into edge-A half
    acc.x += __shfl_down_sync(0xffffffffu, acc.x, 16);
    acc.y += __shfl_down_sync(0xffffffffu, acc.y, 16);
    acc.z += __shfl_down_sync(0xffffffffu, acc.z, 16);
    acc.w += __shfl_down_sync(0xffffffffu, acc.w, 16);

    if (half == 0) {
        __half2 o0 = __floats2half2_rn(fmaxf(acc.x, 0.0f), fmaxf(acc.y, 0.0f));
        __half2 o1 = __floats2half2_rn(fmaxf(acc.z, 0.0f), fmaxf(acc.w, 0.0f));
        uint2 ov;
        ov.x = *reinterpret_cast<uint32_t*>(&o0);
        ov.y = *reinterpret_cast<uint32_t*>(&o1);
        *reinterpret_cast<uint2*>(g_xh + (size_t)w * HID + 4 * hl) = ov;
    }
}

// ---------------------------------------------------------------------------
// 5. Mean pool (grid=512, half2-vectorized loads)
// ---------------------------------------------------------------------------
__global__ void __launch_bounds__(256) pool_kernel() {
    int t = threadIdx.x;
    int c2 = t & 31;
    int grp = t >> 5;
    float2 acc = make_float2(0.0f, 0.0f);
    const __half2* x2 = reinterpret_cast<const __half2*>(g_xh);
    for (int node = blockIdx.x * 8 + grp; node < N_ATOMS; node += gridDim.x * 8) {
        float2 v = __half22float2(x2[(size_t)node * 32 + c2]);
        acc.x += v.x;
        acc.y += v.y;
    }
    __shared__ float2 s[256];
    s[t] = acc;
    __syncthreads();
    if (grp == 0) {
        float2 r = s[c2];
        #pragma unroll
        for (int g = 1; g < 8; g++) {
            r.x += s[g * 32 + c2].x;
            r.y += s[g * 32 + c2].y;
        }
        atomicAdd(&g_pooled[2 * c2], r.x);
        atomicAdd(&g_pooled[2 * c2 + 1], r.y);
    }
}

// ---------------------------------------------------------------------------
// 6. MLP head
// ---------------------------------------------------------------------------
__global__ void head_kernel(const float* __restrict__ W1, const float* __restrict__ b1,
                            const float* __restrict__ W2, const float* __restrict__ b2,
                            float* __restrict__ out) {
    __shared__ float sp[64], sh[64];
    int t = threadIdx.x;
    if (t < 64) sp[t] = g_pooled[t] * (1.0f / (float)N_ATOMS);
    __syncthreads();
    if (t < 64) {
        float a = b1[t];
        #pragma unroll
        for (int k = 0; k < 64; k++) a += sp[k] * W1[k * 64 + t];
        sh[t] = fmaxf(a, 0.0f);
    }
    __syncthreads();
    if (t < 128) {
        float a = b2[t];
        #pragma unroll
        for (int k = 0; k < 64; k++) a += sh[k] * W2[k * 128 + t];
        out[t] = a;
    }
}

// ---------------------------------------------------------------------------
static cudaStream_t g_s1 = nullptr;
static cudaEvent_t  g_evF = nullptr, g_evJ = nullptr;
static int g_init = 0;

extern "C" void kernel_launch(void* const* d_in, const int* in_sizes, int n_in,
                              void* d_out, int out_size) {
    const int*   an  = (const int*)d_in[0];
    const int*   ei  = (const int*)d_in[3];
    const float* emb = (const float*)d_in[4];
    const float* Wl  = (const float*)d_in[5];
    const float* bl  = (const float*)d_in[6];
    const float* Wg  = (const float*)d_in[7];
    const float* bg  = (const float*)d_in[8];
    const float* W1  = (const float*)d_in[9];
    const float* b1  = (const float*)d_in[10];
    const float* W2  = (const float*)d_in[11];
    const float* b2  = (const float*)d_in[12];
    float* out = (float*)d_out;

    if (!g_init) {
        g_init = 1;
        if (cudaStreamCreateWithFlags(&g_s1, cudaStreamNonBlocking) != cudaSuccess) g_s1 = nullptr;
        if (g_s1) {
            cudaEventCreateWithFlags(&g_evF, cudaEventDisableTiming);
            cudaEventCreateWithFlags(&g_evJ, cudaEventDisableTiming);
        }
        cudaFuncSetAttribute(proj_kernel, cudaFuncAttributeMaxDynamicSharedMemorySize, PROJ_SMEM);
    }

    const int embedBlocks = (N_EDGES + 255) / 256;            // 3907 (covers 800k + 1M)
    const int edgeBlocks = (N_EDGES + 255) / 256;             // 3907
    const int gatherBlocks = (N_ATOMS * 32 + 255) / 256;      // 12500
    const bool fork = (g_s1 != nullptr);
    cudaStream_t s1 = fork ? g_s1 : (cudaStream_t)0;

    wconv_kernel<<<400, 256>>>(Wg, Wl);                       // zeros g_cnt/pooled
    embed_kernel<<<embedBlocks, 256>>>(an, emb, ei);          // xh (vectorized) + hist

    if (fork) {
        cudaEventRecord(g_evF, 0);
        cudaStreamWaitEvent(s1, g_evF, 0);
    }
    // sort chain on side stream; overlaps proj0
    scan_a_kernel<<<SCAN_NB, SCAN_T, 0, s1>>>();
    scan_c_kernel<<<SCAN_NB, SCAN_T, 0, s1>>>();
    scatter_kernel<<<edgeBlocks, 256, 0, s1>>>(ei);
    if (fork) cudaEventRecord(g_evJ, s1);

    proj_kernel<<<PROJ_GRID, 256, PROJ_SMEM>>>(0, bg, bl);    // main stream

    if (fork) cudaStreamWaitEvent(0, g_evJ, 0);
    gather_kernel<<<gatherBlocks, 256>>>();

    for (int l = 1; l < 3; l++) {
        proj_kernel<<<PROJ_GRID, 256, PROJ_SMEM>>>(l, bg + l * 64, bl + l * 64);
        gather_kernel<<<gatherBlocks, 256>>>();
    }
    pool_kernel<<<512, 256>>>();
    head_kernel<<<1, 128>>>(W1, b1, W2, b2, out);
}